// round 1
// baseline (speedup 1.0000x reference)
#include <cuda_runtime.h>

// Problem constants
#define SDIM   64
#define CIN    16
#define COUTC  16
#define BATCH  4

// Tiling
#define TY         4    // y rows per block
#define TXT        8    // threads along x
#define XPT        8    // x outputs per thread  (TXT * XPT = 64 = full row)
#define CPT        4    // couts per thread      (4 warps * 4 = 16)
#define NTHREADS 128

// Shared input tile (one cin at a time): z:3, y:TY+2, x:64+2
#define IN_W  66
#define IN_H  (TY + 2)
#define IN_D  3
#define TILE_ELEMS (IN_D * IN_H * IN_W)   // 1188

// Shared weights, transposed: [(cin*3+kd)*3+kh][kw*16 + cout]  -> 16*9*48 = 6912
#define W_ELEMS (CIN * 9 * 48)

__global__ void __launch_bounds__(NTHREADS)
conv3d_kernel(const float* __restrict__ X,
              const float* __restrict__ Wg,
              const float* __restrict__ Bias,
              float* __restrict__ Out)
{
    __shared__ float s_w[W_ELEMS];
    __shared__ float s_bias[COUTC];
    __shared__ float s_in[TILE_ELEMS];

    const int tid = threadIdx.x;
    const int tx  = tid & (TXT - 1);        // 0..7
    const int ty  = (tid >> 3) & (TY - 1);  // 0..3
    const int cg  = tid >> 5;               // warp id = cout group 0..3

    const int z  = blockIdx.x;              // 0..63
    const int y0 = blockIdx.y * TY;         // 0..60
    const int b  = blockIdx.z;              // 0..3

    // ---- Load + transpose weights into shared (broadcast-friendly layout) ----
    for (int g = tid; g < COUTC * CIN * 27; g += NTHREADS) {
        int cout = g / (CIN * 27);
        int rem  = g % (CIN * 27);
        int cin  = rem / 27;
        int k    = rem % 27;        // kd*9 + kh*3 + kw
        int kdh  = k / 3;           // kd*3 + kh
        int kw   = k % 3;
        s_w[(cin * 9 + kdh) * 48 + kw * 16 + cout] = Wg[g];
    }
    if (tid < COUTC) s_bias[tid] = Bias[tid];

    const float* Xb = X + (size_t)b * CIN * (SDIM * SDIM * SDIM);

    float acc[CPT][XPT];
#pragma unroll
    for (int c = 0; c < CPT; ++c)
#pragma unroll
        for (int j = 0; j < XPT; ++j) acc[c][j] = 0.0f;

    for (int cin = 0; cin < CIN; ++cin) {
        __syncthreads();  // previous-iteration readers done (also orders weight fill on cin==0)

        // ---- Cooperative load of the padded input tile for this cin ----
        const float* Xc = Xb + (size_t)cin * (SDIM * SDIM * SDIM);
#pragma unroll 1
        for (int i = tid; i < TILE_ELEMS; i += NTHREADS) {
            int dz = i / (IN_H * IN_W);
            int r  = i % (IN_H * IN_W);
            int dy = r / IN_W;
            int lx = r % IN_W;
            int gz = z  + dz - 1;
            int gy = y0 + dy - 1;
            int gx = lx - 1;
            float v = 0.0f;
            if ((unsigned)gz < SDIM && (unsigned)gy < SDIM && (unsigned)gx < SDIM)
                v = Xc[((size_t)gz * SDIM + gy) * SDIM + gx];
            s_in[i] = v;
        }
        __syncthreads();

        // ---- Register-tiled compute: 4 cout x 8 x, 27 taps ----
        const float* wci = s_w + cin * 9 * 48 + cg * CPT;
#pragma unroll
        for (int kd = 0; kd < 3; ++kd) {
#pragma unroll
            for (int kh = 0; kh < 3; ++kh) {
                const float* row = s_in + (kd * IN_H + ty + kh) * IN_W + tx * XPT;
                float v[XPT + 2];
#pragma unroll
                for (int j = 0; j < XPT + 2; ++j) v[j] = row[j];

                const float* wp = wci + (kd * 3 + kh) * 48;
#pragma unroll
                for (int c = 0; c < CPT; ++c) {
                    const float w0 = wp[c];
                    const float w1 = wp[16 + c];
                    const float w2 = wp[32 + c];
#pragma unroll
                    for (int j = 0; j < XPT; ++j)
                        acc[c][j] += w0 * v[j] + w1 * v[j + 1] + w2 * v[j + 2];
                }
            }
        }
    }

    // ---- Epilogue: bias + vectorized stores ----
    const int x0 = tx * XPT;
    const int y  = y0 + ty;
#pragma unroll
    for (int c = 0; c < CPT; ++c) {
        const int cout = cg * CPT + c;
        const float bb = s_bias[cout];
        float* op = Out + ((((size_t)b * COUTC + cout) * SDIM + z) * SDIM + y) * SDIM + x0;
        float4 o0 = make_float4(acc[c][0] + bb, acc[c][1] + bb, acc[c][2] + bb, acc[c][3] + bb);
        float4 o1 = make_float4(acc[c][4] + bb, acc[c][5] + bb, acc[c][6] + bb, acc[c][7] + bb);
        reinterpret_cast<float4*>(op)[0] = o0;
        reinterpret_cast<float4*>(op)[1] = o1;
    }
}

extern "C" void kernel_launch(void* const* d_in, const int* in_sizes, int n_in,
                              void* d_out, int out_size)
{
    const float* x    = (const float*)d_in[0];
    const float* w    = (const float*)d_in[1];
    const float* bias = (const float*)d_in[2];
    float* out        = (float*)d_out;

    dim3 grid(SDIM, SDIM / TY, BATCH);   // (z, y-tiles, batch) = (64, 16, 4)
    conv3d_kernel<<<grid, NTHREADS>>>(x, w, bias, out);
}

// round 2
// speedup vs baseline: 1.2106x; 1.2106x over previous
#include <cuda_runtime.h>
#include <cstdint>

// Problem constants
#define SDIM   64
#define CIN    16
#define COUTC  16
#define BATCH  4

// Tiling
#define TY         4    // y rows per block
#define TXT        8    // threads along x
#define XPT        8    // x outputs per thread  (TXT * XPT = 64 = full row)
#define CPT        4    // couts per thread      (4 warps * 4 = 16)
#define NTHREADS 128

// Shared input tile (one cin at a time): z:3, y:TY+2, x:64+2  (IN_W even -> 8B-aligned pairs)
#define IN_W  66
#define IN_H  (TY + 2)
#define IN_D  3
#define TILE_ELEMS (IN_D * IN_H * IN_W)   // 1188

// Shared weights, transposed: [(cin*3+kd)*3+kh][kw*16 + cout]  -> 16*9*48 = 6912
#define W_ELEMS (CIN * 9 * 48)

// Packed f32x2 helpers (FFMA2 is only reachable via PTX fma.rn.f32x2)
#define PACKF2(d, lo, hi) \
    asm("mov.b64 %0, {%1, %2};" : "=l"(d) : "f"(lo), "f"(hi))
#define FMAF2(d, a, b, c) \
    asm("fma.rn.f32x2 %0, %1, %2, %3;" : "=l"(d) : "l"(a), "l"(b), "l"(c))
#define UNPACKF2(lo, hi, s) \
    asm("mov.b64 {%0, %1}, %2;" : "=f"(lo), "=f"(hi) : "l"(s))

__global__ void __launch_bounds__(NTHREADS)
conv3d_kernel(const float* __restrict__ X,
              const float* __restrict__ Wg,
              const float* __restrict__ Bias,
              float* __restrict__ Out)
{
    __shared__ float s_w[W_ELEMS];
    __shared__ float s_bias[COUTC];
    __shared__ float s_in[TILE_ELEMS];

    const int tid = threadIdx.x;
    const int tx  = tid & (TXT - 1);        // 0..7
    const int ty  = (tid >> 3) & (TY - 1);  // 0..3
    const int cg  = tid >> 5;               // warp id = cout group 0..3

    const int z  = blockIdx.x;              // 0..63
    const int y0 = blockIdx.y * TY;         // 0..60
    const int b  = blockIdx.z;              // 0..3

    // ---- Load + transpose weights into shared (broadcast + pairwise-cout layout) ----
    for (int g = tid; g < COUTC * CIN * 27; g += NTHREADS) {
        int cout = g / (CIN * 27);
        int rem  = g % (CIN * 27);
        int cin  = rem / 27;
        int k    = rem % 27;        // kd*9 + kh*3 + kw
        int kdh  = k / 3;           // kd*3 + kh
        int kw   = k % 3;
        s_w[(cin * 9 + kdh) * 48 + kw * 16 + cout] = Wg[g];
    }
    if (tid < COUTC) s_bias[tid] = Bias[tid];

    const float* Xb = X + (size_t)b * CIN * (SDIM * SDIM * SDIM);

    // Packed accumulators: accd[cp][j] = (out[cg*4+2cp], out[cg*4+2cp+1]) at x = x0+j
    unsigned long long accd[2][XPT];
#pragma unroll
    for (int cp = 0; cp < 2; ++cp)
#pragma unroll
        for (int j = 0; j < XPT; ++j) accd[cp][j] = 0ull;

    for (int cin = 0; cin < CIN; ++cin) {
        __syncthreads();  // previous-iteration readers done (also orders weight fill on cin==0)

        // ---- Cooperative load of the padded input tile for this cin ----
        const float* Xc = Xb + (size_t)cin * (SDIM * SDIM * SDIM);
#pragma unroll 1
        for (int i = tid; i < TILE_ELEMS; i += NTHREADS) {
            int dz = i / (IN_H * IN_W);
            int r  = i % (IN_H * IN_W);
            int dy = r / IN_W;
            int lx = r % IN_W;
            int gz = z  + dz - 1;
            int gy = y0 + dy - 1;
            int gx = lx - 1;
            float v = 0.0f;
            if ((unsigned)gz < SDIM && (unsigned)gy < SDIM && (unsigned)gx < SDIM)
                v = Xc[((size_t)gz * SDIM + gy) * SDIM + gx];
            s_in[i] = v;
        }
        __syncthreads();

        // ---- Register-tiled compute, packed along cout pairs ----
        const int wbase = cin * 9 * 48 + cg * CPT;
#pragma unroll
        for (int kd = 0; kd < 3; ++kd) {
#pragma unroll
            for (int kh = 0; kh < 3; ++kh) {
                // v row: 10 values as 5 aligned float2 loads, then duplicate each lane
                const float* row = s_in + (kd * IN_H + ty + kh) * IN_W + tx * XPT;
                const float2* r2 = reinterpret_cast<const float2*>(row);
                unsigned long long dup[XPT + 2];
#pragma unroll
                for (int i = 0; i < 5; ++i) {
                    float2 p = r2[i];
                    PACKF2(dup[2 * i],     p.x, p.x);
                    PACKF2(dup[2 * i + 1], p.y, p.y);
                }

                // weights: adjacent-cout pairs, aligned 8B broadcast loads from shared
                const float* wp = s_w + wbase + (kd * 3 + kh) * 48;
                unsigned long long wA[3], wB[3];
#pragma unroll
                for (int kw = 0; kw < 3; ++kw) {
                    wA[kw] = *reinterpret_cast<const unsigned long long*>(wp + kw * 16);
                    wB[kw] = *reinterpret_cast<const unsigned long long*>(wp + kw * 16 + 2);
                }

#pragma unroll
                for (int kw = 0; kw < 3; ++kw) {
#pragma unroll
                    for (int j = 0; j < XPT; ++j) {
                        FMAF2(accd[0][j], dup[j + kw], wA[kw], accd[0][j]);
                        FMAF2(accd[1][j], dup[j + kw], wB[kw], accd[1][j]);
                    }
                }
            }
        }
    }

    // ---- Epilogue: unpack, bias, vectorized stores ----
    const int x0 = tx * XPT;
    const int y  = y0 + ty;
#pragma unroll
    for (int cp = 0; cp < 2; ++cp) {
        float o0[XPT], o1[XPT];
#pragma unroll
        for (int j = 0; j < XPT; ++j) UNPACKF2(o0[j], o1[j], accd[cp][j]);

        const int c0 = cg * CPT + 2 * cp;
        const float b0 = s_bias[c0];
        const float b1 = s_bias[c0 + 1];

        float* op0 = Out + ((((size_t)b * COUTC + c0)     * SDIM + z) * SDIM + y) * SDIM + x0;
        float* op1 = Out + ((((size_t)b * COUTC + c0 + 1) * SDIM + z) * SDIM + y) * SDIM + x0;

        reinterpret_cast<float4*>(op0)[0] = make_float4(o0[0] + b0, o0[1] + b0, o0[2] + b0, o0[3] + b0);
        reinterpret_cast<float4*>(op0)[1] = make_float4(o0[4] + b0, o0[5] + b0, o0[6] + b0, o0[7] + b0);
        reinterpret_cast<float4*>(op1)[0] = make_float4(o1[0] + b1, o1[1] + b1, o1[2] + b1, o1[3] + b1);
        reinterpret_cast<float4*>(op1)[1] = make_float4(o1[4] + b1, o1[5] + b1, o1[6] + b1, o1[7] + b1);
    }
}

extern "C" void kernel_launch(void* const* d_in, const int* in_sizes, int n_in,
                              void* d_out, int out_size)
{
    const float* x    = (const float*)d_in[0];
    const float* w    = (const float*)d_in[1];
    const float* bias = (const float*)d_in[2];
    float* out        = (float*)d_out;

    dim3 grid(SDIM, SDIM / TY, BATCH);   // (z, y-tiles, batch) = (64, 16, 4)
    conv3d_kernel<<<grid, NTHREADS>>>(x, w, bias, out);
}

// round 3
// speedup vs baseline: 1.8280x; 1.5100x over previous
#include <cuda_runtime.h>
#include <cstdint>

// Problem constants
#define SDIM   64
#define CIN    16
#define COUTC  16
#define BATCH  4

// Tiling
#define TY         4
#define TXT        8
#define XPT        8
#define CPT        4
#define NTHREADS 128

// Shared input tile (one cin): z:3, y:TY+2, x:66 (even -> 8B-aligned float2 rows)
#define IN_W  66
#define IN_H  (TY + 2)
#define IN_D  3
#define TILE_ELEMS (IN_D * IN_H * IN_W)         // 1188
#define SLOTS_PER_THREAD ((TILE_ELEMS + NTHREADS - 1) / NTHREADS)  // 10

// Shared weights, transposed: [(cin*3+kd)*3+kh][kw*16 + cout]
#define W_ELEMS (CIN * 9 * 48)

#define PACKF2(d, lo, hi) \
    asm("mov.b64 %0, {%1, %2};" : "=l"(d) : "f"(lo), "f"(hi))
#define FMAF2(d, a, b, c) \
    asm("fma.rn.f32x2 %0, %1, %2, %3;" : "=l"(d) : "l"(a), "l"(b), "l"(c))
#define UNPACKF2(lo, hi, s) \
    asm("mov.b64 {%0, %1}, %2;" : "=f"(lo), "=f"(hi) : "l"(s))

__device__ __forceinline__ uint32_t smem_u32(const void* p) {
    return (uint32_t)__cvta_generic_to_shared(p);
}

__global__ void __launch_bounds__(NTHREADS)
conv3d_kernel(const float* __restrict__ X,
              const float* __restrict__ Wg,
              const float* __restrict__ Bias,
              float* __restrict__ Out)
{
    __shared__ float s_w[W_ELEMS];
    __shared__ float s_bias[COUTC];
    __shared__ float s_in[2][TILE_ELEMS];

    const int tid = threadIdx.x;
    const int tx  = tid & (TXT - 1);
    const int ty  = (tid >> 3) & (TY - 1);
    const int cg  = tid >> 5;

    const int z  = blockIdx.x;
    const int y0 = blockIdx.y * TY;
    const int b  = blockIdx.z;

    // ---- Weights: load + transpose into shared ----
    for (int g = tid; g < COUTC * CIN * 27; g += NTHREADS) {
        int cout = g / (CIN * 27);
        int rem  = g % (CIN * 27);
        int cin  = rem / 27;
        int k    = rem % 27;
        int kdh  = k / 3;
        int kw   = k % 3;
        s_w[(cin * 9 + kdh) * 48 + kw * 16 + cout] = Wg[g];
    }
    if (tid < COUTC) s_bias[tid] = Bias[tid];

    // ---- Precompute this thread's tile-slot source offsets (cin-invariant) ----
    // slot i = tid + k*128 ; src plane offset or -1 if halo-out-of-range.
    int soff[SLOTS_PER_THREAD];
#pragma unroll
    for (int k = 0; k < SLOTS_PER_THREAD; ++k) {
        int i = tid + k * NTHREADS;
        int off = -1;
        if (i < TILE_ELEMS) {
            int dz = i / (IN_H * IN_W);
            int r  = i % (IN_H * IN_W);
            int dy = r / IN_W;
            int lx = r % IN_W;
            int gz = z  + dz - 1;
            int gy = y0 + dy - 1;
            int gx = lx - 1;
            if ((unsigned)gz < SDIM && (unsigned)gy < SDIM && (unsigned)gx < SDIM)
                off = ((gz * SDIM + gy) * SDIM + gx);
            else {
                // zero invalid slot once in BOTH buffers; never rewritten after
                s_in[0][i] = 0.0f;
                s_in[1][i] = 0.0f;
            }
        }
        soff[k] = off;
    }
    __syncthreads();   // zeros + weights visible before any compute / overwrite

    const float* Xb = X + (size_t)b * CIN * (SDIM * SDIM * SDIM);

    // ---- Prologue: async-load tile for cin=0 into buffer 0 ----
    {
        const float* Xc = Xb;
#pragma unroll
        for (int k = 0; k < SLOTS_PER_THREAD; ++k) {
            if (soff[k] >= 0) {
                uint32_t dst = smem_u32(&s_in[0][tid + k * NTHREADS]);
                const float* src = Xc + soff[k];
                asm volatile("cp.async.ca.shared.global [%0], [%1], 4;"
                             :: "r"(dst), "l"(src));
            }
        }
        asm volatile("cp.async.commit_group;");
    }

    unsigned long long accd[2][XPT];
#pragma unroll
    for (int cp = 0; cp < 2; ++cp)
#pragma unroll
        for (int j = 0; j < XPT; ++j) accd[cp][j] = 0ull;

#pragma unroll 1
    for (int cin = 0; cin < CIN; ++cin) {
        // wait for this cin's tile; barrier also guarantees everyone is done
        // reading the buffer we are about to overwrite (read 2 iterations ago)
        asm volatile("cp.async.wait_group 0;");
        __syncthreads();

        // issue next cin's loads into the other buffer
        if (cin + 1 < CIN) {
            const float* Xc = Xb + (size_t)(cin + 1) * (SDIM * SDIM * SDIM);
            float* buf = s_in[(cin + 1) & 1];
#pragma unroll
            for (int k = 0; k < SLOTS_PER_THREAD; ++k) {
                if (soff[k] >= 0) {
                    uint32_t dst = smem_u32(&buf[tid + k * NTHREADS]);
                    const float* src = Xc + soff[k];
                    asm volatile("cp.async.ca.shared.global [%0], [%1], 4;"
                                 :: "r"(dst), "l"(src));
                }
            }
            asm volatile("cp.async.commit_group;");
        }

        // ---- Compute on current buffer: FFMA2 over cout pairs ----
        const float* cur = s_in[cin & 1];
        const int wbase = cin * 9 * 48 + cg * CPT;
#pragma unroll
        for (int kd = 0; kd < 3; ++kd) {
#pragma unroll
            for (int kh = 0; kh < 3; ++kh) {
                const float* row = cur + (kd * IN_H + ty + kh) * IN_W + tx * XPT;
                const float2* r2 = reinterpret_cast<const float2*>(row);
                unsigned long long dup[XPT + 2];
#pragma unroll
                for (int i = 0; i < 5; ++i) {
                    float2 p = r2[i];
                    PACKF2(dup[2 * i],     p.x, p.x);
                    PACKF2(dup[2 * i + 1], p.y, p.y);
                }

                const float* wp = s_w + wbase + (kd * 3 + kh) * 48;
                unsigned long long wA[3], wB[3];
#pragma unroll
                for (int kw = 0; kw < 3; ++kw) {
                    wA[kw] = *reinterpret_cast<const unsigned long long*>(wp + kw * 16);
                    wB[kw] = *reinterpret_cast<const unsigned long long*>(wp + kw * 16 + 2);
                }

#pragma unroll
                for (int kw = 0; kw < 3; ++kw) {
#pragma unroll
                    for (int j = 0; j < XPT; ++j) {
                        FMAF2(accd[0][j], dup[j + kw], wA[kw], accd[0][j]);
                        FMAF2(accd[1][j], dup[j + kw], wB[kw], accd[1][j]);
                    }
                }
            }
        }
    }

    // ---- Epilogue ----
    const int x0 = tx * XPT;
    const int y  = y0 + ty;
#pragma unroll
    for (int cp = 0; cp < 2; ++cp) {
        float o0[XPT], o1[XPT];
#pragma unroll
        for (int j = 0; j < XPT; ++j) UNPACKF2(o0[j], o1[j], accd[cp][j]);

        const int c0 = cg * CPT + 2 * cp;
        const float b0 = s_bias[c0];
        const float b1 = s_bias[c0 + 1];

        float* op0 = Out + ((((size_t)b * COUTC + c0)     * SDIM + z) * SDIM + y) * SDIM + x0;
        float* op1 = Out + ((((size_t)b * COUTC + c0 + 1) * SDIM + z) * SDIM + y) * SDIM + x0;

        reinterpret_cast<float4*>(op0)[0] = make_float4(o0[0] + b0, o0[1] + b0, o0[2] + b0, o0[3] + b0);
        reinterpret_cast<float4*>(op0)[1] = make_float4(o0[4] + b0, o0[5] + b0, o0[6] + b0, o0[7] + b0);
        reinterpret_cast<float4*>(op1)[0] = make_float4(o1[0] + b1, o1[1] + b1, o1[2] + b1, o1[3] + b1);
        reinterpret_cast<float4*>(op1)[1] = make_float4(o1[4] + b1, o1[5] + b1, o1[6] + b1, o1[7] + b1);
    }
}

extern "C" void kernel_launch(void* const* d_in, const int* in_sizes, int n_in,
                              void* d_out, int out_size)
{
    const float* x    = (const float*)d_in[0];
    const float* w    = (const float*)d_in[1];
    const float* bias = (const float*)d_in[2];
    float* out        = (float*)d_out;

    dim3 grid(SDIM, SDIM / TY, BATCH);
    conv3d_kernel<<<grid, NTHREADS>>>(x, w, bias, out);
}